// round 2
// baseline (speedup 1.0000x reference)
#include <cuda_runtime.h>
#include <math.h>

#define T   2048
#define H   16
#define DN  128
#define DR  64
#define DV  128
#define QL  1536
#define KVL 512
#define HID 5120
#define DQK 192            // DN + DR
#define DKV 256            // DN + DV
#define EPS 1e-6f
#define THETA 10000.0f

// ---------------- scratch (static __device__ — no runtime allocation) ----------------
__device__ float g_qa   [(size_t)T * QL];
__device__ float g_qan  [(size_t)T * QL];
__device__ float g_q    [(size_t)T * H * DQK];
__device__ float g_kv   [(size_t)T * (KVL + DR)];
__device__ float g_ckv  [(size_t)T * KVL];
__device__ float g_kvb  [(size_t)T * H * DKV];
__device__ float g_qcat [(size_t)H * T * DQK];
__device__ float g_kcat [(size_t)H * T * DQK];
__device__ float g_v    [(size_t)H * T * DV];
__device__ float g_scores[(size_t)H * T * T];     // 268 MB
__device__ float g_attnout[(size_t)T * H * DV];

// ---------------- generic SGEMM: C = A * B (or A * B^T), batched over z ----------------
// BM=BN=128, BK=8, 256 threads, 8x8 per thread.
// CAUSAL: skip output blocks strictly above the diagonal (scores GEMM).
// KLIM:   truncate the K loop at (blockIdx.y+1)*128 (attn@V GEMM; attn rows are
//         zero beyond the diagonal so the tail contributes nothing).
template<int TRANSB, int CAUSAL, int KLIM>
__global__ __launch_bounds__(256)
void sgemm_kernel(int M, int N, int K,
                  const float* __restrict__ A, int lda, size_t strideA,
                  const float* __restrict__ B, int ldb, size_t strideB,
                  float* __restrict__ C, int ldc, size_t strideC)
{
    if (CAUSAL) {
        // rows covered: [by*128, by*128+127]; cols: [bx*128, ...]. If the whole
        // col block is > max row, every output lies above the diagonal -> dead.
        if ((int)blockIdx.x * 128 > (int)blockIdx.y * 128 + 127) return;
    }
    int Keff = K;
    if (KLIM) {
        int lim = ((int)blockIdx.y + 1) * 128;
        if (lim < Keff) Keff = lim;
    }

    A += (size_t)blockIdx.z * strideA;
    B += (size_t)blockIdx.z * strideB;
    C += (size_t)blockIdx.z * strideC;

    __shared__ float As[8][128];
    __shared__ float Bs[8][128];

    const int tid = threadIdx.x;
    const int tx  = tid & 15;          // 0..15  (N dir)
    const int ty  = tid >> 4;          // 0..15  (M dir)
    const int row0 = blockIdx.y * 128 + ty * 8;
    const int col0 = blockIdx.x * 128 + tx * 8;

    float acc[8][8];
    #pragma unroll
    for (int i = 0; i < 8; i++)
        #pragma unroll
        for (int j = 0; j < 8; j++) acc[i][j] = 0.f;

    // A-tile load map: thread -> (row = tid/2, k = (tid&1)*4 .. +3)
    const int aRow = tid >> 1;
    const int aK   = (tid & 1) * 4;
    // B-tile (NN) load map: thread -> (k = tid/32, col = (tid&31)*4 .. +3)
    const int bK   = tid >> 5;
    const int bCol = (tid & 31) * 4;
    // B-tile (NT) load map: same shape as A (B is [N,K] row-major)
    const int btRow = tid >> 1;
    const int btK   = (tid & 1) * 4;

    for (int k0 = 0; k0 < Keff; k0 += 8) {
        {   // load A
            const int gr = blockIdx.y * 128 + aRow;
            #pragma unroll
            for (int i = 0; i < 4; i++) {
                const int gk = k0 + aK + i;
                float v = 0.f;
                if (gr < M && gk < K) v = A[(size_t)gr * lda + gk];
                As[aK + i][aRow] = v;
            }
        }
        if (TRANSB) {
            const int gc = blockIdx.x * 128 + btRow;
            #pragma unroll
            for (int i = 0; i < 4; i++) {
                const int gk = k0 + btK + i;
                float v = 0.f;
                if (gc < N && gk < K) v = B[(size_t)gc * ldb + gk];
                Bs[btK + i][btRow] = v;
            }
        } else {
            const int gk = k0 + bK;
            const int gc = blockIdx.x * 128 + bCol;
            #pragma unroll
            for (int i = 0; i < 4; i++) {
                float v = 0.f;
                if (gk < K && (gc + i) < N) v = B[(size_t)gk * ldb + gc + i];
                Bs[bK][bCol + i] = v;
            }
        }
        __syncthreads();

        #pragma unroll
        for (int k = 0; k < 8; k++) {
            float4 a0 = *reinterpret_cast<const float4*>(&As[k][ty * 8]);
            float4 a1 = *reinterpret_cast<const float4*>(&As[k][ty * 8 + 4]);
            float4 b0 = *reinterpret_cast<const float4*>(&Bs[k][tx * 8]);
            float4 b1 = *reinterpret_cast<const float4*>(&Bs[k][tx * 8 + 4]);
            float a[8] = {a0.x, a0.y, a0.z, a0.w, a1.x, a1.y, a1.z, a1.w};
            float b[8] = {b0.x, b0.y, b0.z, b0.w, b1.x, b1.y, b1.z, b1.w};
            #pragma unroll
            for (int i = 0; i < 8; i++)
                #pragma unroll
                for (int j = 0; j < 8; j++)
                    acc[i][j] = fmaf(a[i], b[j], acc[i][j]);
        }
        __syncthreads();
    }

    #pragma unroll
    for (int i = 0; i < 8; i++) {
        const int r = row0 + i;
        if (r >= M) break;
        #pragma unroll
        for (int j = 0; j < 8; j++) {
            const int c = col0 + j;
            if (c < N) C[(size_t)r * ldc + c] = acc[i][j];
        }
    }
}

// ---------------- RMSNorm: one block per row ----------------
__global__ __launch_bounds__(256)
void rmsnorm_kernel(const float* __restrict__ x, const float* __restrict__ w,
                    float* __restrict__ y, int n, int ld_in, int ld_out)
{
    const int row = blockIdx.x;
    const float* xr = x + (size_t)row * ld_in;
    float* yr = y + (size_t)row * ld_out;

    float s = 0.f;
    for (int i = threadIdx.x; i < n; i += blockDim.x) { float v = xr[i]; s += v * v; }

    __shared__ float red[32];
    #pragma unroll
    for (int o = 16; o; o >>= 1) s += __shfl_xor_sync(~0u, s, o);
    if ((threadIdx.x & 31) == 0) red[threadIdx.x >> 5] = s;
    __syncthreads();
    if (threadIdx.x < 32) {
        s = (threadIdx.x < (blockDim.x >> 5)) ? red[threadIdx.x] : 0.f;
        #pragma unroll
        for (int o = 16; o; o >>= 1) s += __shfl_xor_sync(~0u, s, o);
        if (threadIdx.x == 0) red[0] = s;
    }
    __syncthreads();
    const float r = rsqrtf(red[0] / (float)n + EPS);
    for (int i = threadIdx.x; i < n; i += blockDim.x) yr[i] = xr[i] * r * w[i];
}

// ---------------- pack: build qcat (roped+scaled), kcat (roped), v; head-major ----------------
__global__ __launch_bounds__(256)
void pack_kernel()
{
    const int t = blockIdx.x;
    const float pos = (float)t;     // positions == arange(T) by construction

    __shared__ float cs[DR / 2], sn[DR / 2];
    if (threadIdx.x < DR / 2) {
        const float inv = powf(THETA, -(float)(2 * threadIdx.x) / (float)DR);
        const float f = pos * inv;
        cs[threadIdx.x] = cosf(f);
        sn[threadIdx.x] = sinf(f);
    }
    __syncthreads();

    const float scale = rsqrtf((float)DQK);

    for (int idx = threadIdx.x; idx < H * DQK; idx += blockDim.x) {
        const int h = idx / DQK, d = idx % DQK;
        // ----- qcat -----
        float qv;
        const size_t qbase = (size_t)t * (H * DQK) + (size_t)h * DQK;
        if (d < DN) {
            qv = g_q[qbase + d];
        } else {
            const int j = d - DN, i = j >> 1;
            const float x1 = g_q[qbase + DN + 2 * i];
            const float x2 = g_q[qbase + DN + 2 * i + 1];
            qv = (j & 1) ? (x2 * cs[i] + x1 * sn[i]) : (x1 * cs[i] - x2 * sn[i]);
        }
        g_qcat[((size_t)h * T + t) * DQK + d] = qv * scale;
        // ----- kcat -----
        float kvv;
        if (d < DN) {
            kvv = g_kvb[(size_t)t * (H * DKV) + (size_t)h * DKV + d];
        } else {
            const int j = d - DN, i = j >> 1;
            const float x1 = g_kv[(size_t)t * (KVL + DR) + KVL + 2 * i];
            const float x2 = g_kv[(size_t)t * (KVL + DR) + KVL + 2 * i + 1];
            kvv = (j & 1) ? (x2 * cs[i] + x1 * sn[i]) : (x1 * cs[i] - x2 * sn[i]);
        }
        g_kcat[((size_t)h * T + t) * DQK + d] = kvv;
    }
    for (int idx = threadIdx.x; idx < H * DV; idx += blockDim.x) {
        const int h = idx / DV, d = idx % DV;
        g_v[((size_t)h * T + t) * DV + d] =
            g_kvb[(size_t)t * (H * DKV) + (size_t)h * DKV + DN + d];
    }
}

// ---------------- causal softmax over row t (valid length t+1), zero-fill the tail ----------------
__global__ __launch_bounds__(256)
void softmax_kernel()
{
    const int t = blockIdx.x;
    const int h = blockIdx.y;
    float* row = g_scores + ((size_t)h * T + t) * T;
    const int n = t + 1;

    __shared__ float red[32];

    // max
    float m = -INFINITY;
    for (int i = threadIdx.x; i < n; i += blockDim.x) m = fmaxf(m, row[i]);
    #pragma unroll
    for (int o = 16; o; o >>= 1) m = fmaxf(m, __shfl_xor_sync(~0u, m, o));
    if ((threadIdx.x & 31) == 0) red[threadIdx.x >> 5] = m;
    __syncthreads();
    if (threadIdx.x < 32) {
        m = (threadIdx.x < (blockDim.x >> 5)) ? red[threadIdx.x] : -INFINITY;
        #pragma unroll
        for (int o = 16; o; o >>= 1) m = fmaxf(m, __shfl_xor_sync(~0u, m, o));
        if (threadIdx.x == 0) red[0] = m;
    }
    __syncthreads();
    m = red[0];
    __syncthreads();

    // exp + sum
    float s = 0.f;
    for (int i = threadIdx.x; i < n; i += blockDim.x) {
        const float e = expf(row[i] - m);
        row[i] = e;
        s += e;
    }
    #pragma unroll
    for (int o = 16; o; o >>= 1) s += __shfl_xor_sync(~0u, s, o);
    if ((threadIdx.x & 31) == 0) red[threadIdx.x >> 5] = s;
    __syncthreads();
    if (threadIdx.x < 32) {
        s = (threadIdx.x < (blockDim.x >> 5)) ? red[threadIdx.x] : 0.f;
        #pragma unroll
        for (int o = 16; o; o >>= 1) s += __shfl_xor_sync(~0u, s, o);
        if (threadIdx.x == 0) red[0] = s;
    }
    __syncthreads();
    const float inv = 1.f / red[0];

    for (int i = threadIdx.x; i < n; i += blockDim.x) row[i] *= inv;
    for (int i = n + threadIdx.x; i < T; i += blockDim.x) row[i] = 0.f;  // tail for dense attn@V
}

// ---------------- launch ----------------
static inline dim3 gemm_grid(int M, int N, int Z) {
    return dim3((N + 127) / 128, (M + 127) / 128, Z);
}

extern "C" void kernel_launch(void* const* d_in, const int* in_sizes, int n_in,
                              void* d_out, int out_size)
{
    (void)in_sizes; (void)n_in; (void)out_size;
    const float* hidden  = (const float*)d_in[1];
    const float* wq_a    = (const float*)d_in[2];
    const float* q_a_ln  = (const float*)d_in[3];
    const float* wq_b    = (const float*)d_in[4];
    const float* wkv_a   = (const float*)d_in[5];
    const float* kv_a_ln = (const float*)d_in[6];
    const float* wkv_b   = (const float*)d_in[7];
    const float* wo      = (const float*)d_in[8];
    float* out = (float*)d_out;

    float *qa, *qan, *q, *kv, *ckv, *kvb, *qcat, *kcat, *v, *scores, *attnout;
    cudaGetSymbolAddress((void**)&qa, g_qa);
    cudaGetSymbolAddress((void**)&qan, g_qan);
    cudaGetSymbolAddress((void**)&q, g_q);
    cudaGetSymbolAddress((void**)&kv, g_kv);
    cudaGetSymbolAddress((void**)&ckv, g_ckv);
    cudaGetSymbolAddress((void**)&kvb, g_kvb);
    cudaGetSymbolAddress((void**)&qcat, g_qcat);
    cudaGetSymbolAddress((void**)&kcat, g_kcat);
    cudaGetSymbolAddress((void**)&v, g_v);
    cudaGetSymbolAddress((void**)&scores, g_scores);
    cudaGetSymbolAddress((void**)&attnout, g_attnout);

    // 1) q_a = hidden @ wq_a          [T,HID]x[HID,QL]
    sgemm_kernel<0,0,0><<<gemm_grid(T, QL, 1), 256>>>(T, QL, HID, hidden, HID, 0, wq_a, QL, 0, qa, QL, 0);
    // 2) rmsnorm(q_a)
    rmsnorm_kernel<<<T, 256>>>(qa, q_a_ln, qan, QL, QL, QL);
    // 3) q = qan @ wq_b               [T,QL]x[QL,H*DQK]
    sgemm_kernel<0,0,0><<<gemm_grid(T, H * DQK, 1), 256>>>(T, H * DQK, QL, qan, QL, 0, wq_b, H * DQK, 0, q, H * DQK, 0);
    // 4) kv = hidden @ wkv_a          [T,HID]x[HID,KVL+DR]
    sgemm_kernel<0,0,0><<<gemm_grid(T, KVL + DR, 1), 256>>>(T, KVL + DR, HID, hidden, HID, 0, wkv_a, KVL + DR, 0, kv, KVL + DR, 0);
    // 5) c_kv = rmsnorm(kv[:, :KVL])
    rmsnorm_kernel<<<T, 256>>>(kv, kv_a_ln, ckv, KVL, KVL + DR, KVL);
    // 6) kvb = c_kv @ wkv_b           [T,KVL]x[KVL,H*DKV]
    sgemm_kernel<0,0,0><<<gemm_grid(T, H * DKV, 1), 256>>>(T, H * DKV, KVL, ckv, KVL, 0, wkv_b, H * DKV, 0, kvb, H * DKV, 0);
    // 7) pack qcat/kcat/v with fused RoPE + scale
    pack_kernel<<<T, 256>>>();
    // 8) scores[h] = qcat[h] @ kcat[h]^T   (batched NT, causal block skip)
    sgemm_kernel<1,1,0><<<gemm_grid(T, T, H), 256>>>(T, T, DQK,
        qcat, DQK, (size_t)T * DQK, kcat, DQK, (size_t)T * DQK, scores, T, (size_t)T * T);
    // 9) causal softmax (+ zero tail)
    softmax_kernel<<<dim3(T, H), 256>>>();
    // 10) attnout[:, h*DV:(h+1)*DV] = attn[h] @ v[h]   (batched NN, K truncated at diagonal)
    sgemm_kernel<0,0,1><<<gemm_grid(T, DV, H), 256>>>(T, DV, T,
        scores, T, (size_t)T * T, v, DV, (size_t)T * DV, attnout, H * DV, (size_t)DV);
    // 11) out = attnout @ wo          [T,H*DV]x[H*DV,HID]
    sgemm_kernel<0,0,0><<<gemm_grid(T, HID, 1), 256>>>(T, HID, H * DV, attnout, H * DV, 0, wo, HID, 0, out, HID, 0);
}

// round 3
// speedup vs baseline: 3.7781x; 3.7781x over previous
#include <cuda_runtime.h>
#include <math.h>
#include <stdint.h>

#define T   2048
#define H   16
#define DN  128
#define DR  64
#define DV  128
#define QL  1536
#define KVL 512
#define HID 5120
#define DQK 192            // DN + DR
#define DKV 256            // DN + DV
#define EPS 1e-6f
#define THETA 10000.0f

// ---------------- scratch (static __device__ — no runtime allocation) ----------------
__device__ float g_qa   [(size_t)T * QL];
__device__ float g_qan  [(size_t)T * QL];
__device__ float g_q    [(size_t)T * H * DQK];
__device__ float g_kv   [(size_t)T * (KVL + DR)];
__device__ float g_ckv  [(size_t)T * KVL];
__device__ float g_kvb  [(size_t)T * H * DKV];
__device__ float g_qcat [(size_t)H * T * DQK];
__device__ float g_kcat [(size_t)H * T * DQK];
__device__ float g_v    [(size_t)H * T * DV];
__device__ float g_scores[(size_t)H * T * T];     // 268 MB
__device__ float g_attnout[(size_t)T * H * DV];

// ---------------- helpers ----------------
__device__ __forceinline__ float to_tf32(float x) {
    float r;
    asm("cvt.rna.tf32.f32 %0, %1;" : "=f"(r) : "f"(x));
    return r;
}

__device__ __forceinline__ void mma_tf32(float* d, const float* a, const float* b) {
    asm volatile(
        "mma.sync.aligned.m16n8k8.row.col.f32.tf32.tf32.f32 "
        "{%0,%1,%2,%3},{%4,%5,%6,%7},{%8,%9},{%0,%1,%2,%3};"
        : "+f"(d[0]), "+f"(d[1]), "+f"(d[2]), "+f"(d[3])
        : "r"(__float_as_uint(a[0])), "r"(__float_as_uint(a[1])),
          "r"(__float_as_uint(a[2])), "r"(__float_as_uint(a[3])),
          "r"(__float_as_uint(b[0])), "r"(__float_as_uint(b[1])));
}

// ---------------- tf32 tensor-core GEMM: C = A * B (or A * B^T), batched over z ----
// BM=BN=128, BK=32, 256 threads (8 warps, 2x4), warp tile 64x32.
// CAUSAL: skip output blocks strictly above the diagonal.
// KLIM:   truncate K at (blockIdx.y+1)*128 (attn rows are zero past the diagonal).
#define AS_STR 36   // As[m][k], bank = (4m+k)%32 -> conflict-free frag loads
#define BS_NN  136  // Bs[k][n], bank = (8k+n)%32 -> conflict-free
#define BS_NT  36   // Bs[n][k], bank = (4n+k)%32 -> conflict-free

template<int TRANSB, int CAUSAL, int KLIM>
__global__ __launch_bounds__(256)
void mma_gemm(int M, int N, int K,
              const float* __restrict__ A, int lda, size_t strideA,
              const float* __restrict__ B, int ldb, size_t strideB,
              float* __restrict__ C, int ldc, size_t strideC)
{
    if (CAUSAL) {
        if ((int)blockIdx.x * 128 > (int)blockIdx.y * 128 + 127) return;
    }
    int Keff = K;
    if (KLIM) {
        int lim = ((int)blockIdx.y + 1) * 128;
        if (lim < Keff) Keff = lim;
    }

    A += (size_t)blockIdx.z * strideA;
    B += (size_t)blockIdx.z * strideB;
    C += (size_t)blockIdx.z * strideC;

    __shared__ float As[128 * AS_STR];
    __shared__ float Bs[128 * 36];      // max(128*36, 32*136)

    const int tid  = threadIdx.x;
    const int lane = tid & 31;
    const int warp = tid >> 5;
    const int wm   = warp >> 2;         // 0..1
    const int wn   = warp & 3;          // 0..3
    const int row0 = blockIdx.y * 128;
    const int col0 = blockIdx.x * 128;
    const bool fullN = (col0 + 128) <= N;

    float acc[4][4][4];
    #pragma unroll
    for (int mi = 0; mi < 4; mi++)
        #pragma unroll
        for (int ni = 0; ni < 4; ni++)
            #pragma unroll
            for (int f = 0; f < 4; f++) acc[mi][ni][f] = 0.f;

    float4 stA[4], stB[4];

    // ---- global loads into staging regs ----
    auto ldgA = [&](int k0) {
        #pragma unroll
        for (int i = 0; i < 4; i++) {
            int idx = tid + 256 * i, r = idx >> 3, j = idx & 7;
            stA[i] = *reinterpret_cast<const float4*>(
                &A[(size_t)(row0 + r) * lda + k0 + 4 * j]);
        }
    };
    auto ldgB = [&](int k0) {
        if (TRANSB) {
            #pragma unroll
            for (int i = 0; i < 4; i++) {
                int idx = tid + 256 * i, n = idx >> 3, j = idx & 7;
                if (fullN || (col0 + n) < N)
                    stB[i] = *reinterpret_cast<const float4*>(
                        &B[(size_t)(col0 + n) * ldb + k0 + 4 * j]);
                else
                    stB[i] = make_float4(0.f, 0.f, 0.f, 0.f);
            }
        } else {
            #pragma unroll
            for (int i = 0; i < 4; i++) {
                int idx = tid + 256 * i, k = idx >> 5, j = idx & 31;
                int gc = col0 + 4 * j;
                if (fullN) {
                    stB[i] = *reinterpret_cast<const float4*>(
                        &B[(size_t)(k0 + k) * ldb + gc]);
                } else {
                    float4 v = make_float4(0.f, 0.f, 0.f, 0.f);
                    const float* bp = &B[(size_t)(k0 + k) * ldb];
                    if (gc + 0 < N) v.x = bp[gc + 0];
                    if (gc + 1 < N) v.y = bp[gc + 1];
                    if (gc + 2 < N) v.z = bp[gc + 2];
                    if (gc + 3 < N) v.w = bp[gc + 3];
                    stB[i] = v;
                }
            }
        }
    };

    // ---- staging regs -> SMEM (with tf32 rounding) ----
    auto stsA = [&]() {
        #pragma unroll
        for (int i = 0; i < 4; i++) {
            int idx = tid + 256 * i, r = idx >> 3, j = idx & 7;
            *reinterpret_cast<float4*>(&As[r * AS_STR + 4 * j]) =
                make_float4(to_tf32(stA[i].x), to_tf32(stA[i].y),
                            to_tf32(stA[i].z), to_tf32(stA[i].w));
        }
    };
    auto stsB = [&]() {
        if (TRANSB) {
            #pragma unroll
            for (int i = 0; i < 4; i++) {
                int idx = tid + 256 * i, n = idx >> 3, j = idx & 7;
                *reinterpret_cast<float4*>(&Bs[n * BS_NT + 4 * j]) =
                    make_float4(to_tf32(stB[i].x), to_tf32(stB[i].y),
                                to_tf32(stB[i].z), to_tf32(stB[i].w));
            }
        } else {
            #pragma unroll
            for (int i = 0; i < 4; i++) {
                int idx = tid + 256 * i, k = idx >> 5, j = idx & 31;
                *reinterpret_cast<float4*>(&Bs[k * BS_NN + 4 * j]) =
                    make_float4(to_tf32(stB[i].x), to_tf32(stB[i].y),
                                to_tf32(stB[i].z), to_tf32(stB[i].w));
            }
        }
    };

    auto compute = [&]() {
        #pragma unroll
        for (int ks = 0; ks < 4; ks++) {
            const int kq = ks * 8 + (lane & 3);
            float a[4][4], b[4][2];
            #pragma unroll
            for (int mi = 0; mi < 4; mi++) {
                int r = wm * 64 + mi * 16 + (lane >> 2);
                a[mi][0] = As[r * AS_STR + kq];
                a[mi][1] = As[(r + 8) * AS_STR + kq];
                a[mi][2] = As[r * AS_STR + kq + 4];
                a[mi][3] = As[(r + 8) * AS_STR + kq + 4];
            }
            #pragma unroll
            for (int ni = 0; ni < 4; ni++) {
                int n = wn * 32 + ni * 8 + (lane >> 2);
                if (TRANSB) {
                    b[ni][0] = Bs[n * BS_NT + kq];
                    b[ni][1] = Bs[n * BS_NT + kq + 4];
                } else {
                    b[ni][0] = Bs[kq * BS_NN + n];
                    b[ni][1] = Bs[(kq + 4) * BS_NN + n];
                }
            }
            #pragma unroll
            for (int mi = 0; mi < 4; mi++)
                #pragma unroll
                for (int ni = 0; ni < 4; ni++)
                    mma_tf32(acc[mi][ni], a[mi], b[ni]);
        }
    };

    // ---- main loop ----
    const int nt = Keff / 32;
    ldgA(0); ldgB(0);
    stsA(); stsB();
    __syncthreads();
    for (int t = 0; t < nt; t++) {
        if (t + 1 < nt) { ldgA((t + 1) * 32); ldgB((t + 1) * 32); }
        compute();
        if (t + 1 < nt) {
            __syncthreads();
            stsA(); stsB();
            __syncthreads();
        }
    }

    // ---- epilogue ----
    #pragma unroll
    for (int mi = 0; mi < 4; mi++) {
        #pragma unroll
        for (int ni = 0; ni < 4; ni++) {
            int r  = row0 + wm * 64 + mi * 16 + (lane >> 2);
            int cc = col0 + wn * 32 + ni * 8 + 2 * (lane & 3);
            if (cc < N) {
                *reinterpret_cast<float2*>(&C[(size_t)r * ldc + cc]) =
                    make_float2(acc[mi][ni][0], acc[mi][ni][1]);
                *reinterpret_cast<float2*>(&C[(size_t)(r + 8) * ldc + cc]) =
                    make_float2(acc[mi][ni][2], acc[mi][ni][3]);
            }
        }
    }
}

// ---------------- RMSNorm: one block per row ----------------
__global__ __launch_bounds__(256)
void rmsnorm_kernel(const float* __restrict__ x, const float* __restrict__ w,
                    float* __restrict__ y, int n, int ld_in, int ld_out)
{
    const int row = blockIdx.x;
    const float* xr = x + (size_t)row * ld_in;
    float* yr = y + (size_t)row * ld_out;

    float s = 0.f;
    for (int i = threadIdx.x; i < n; i += blockDim.x) { float v = xr[i]; s += v * v; }

    __shared__ float red[32];
    #pragma unroll
    for (int o = 16; o; o >>= 1) s += __shfl_xor_sync(~0u, s, o);
    if ((threadIdx.x & 31) == 0) red[threadIdx.x >> 5] = s;
    __syncthreads();
    if (threadIdx.x < 32) {
        s = (threadIdx.x < (blockDim.x >> 5)) ? red[threadIdx.x] : 0.f;
        #pragma unroll
        for (int o = 16; o; o >>= 1) s += __shfl_xor_sync(~0u, s, o);
        if (threadIdx.x == 0) red[0] = s;
    }
    __syncthreads();
    const float r = rsqrtf(red[0] / (float)n + EPS);
    for (int i = threadIdx.x; i < n; i += blockDim.x) yr[i] = xr[i] * r * w[i];
}

// ---------------- pack: build qcat (roped+scaled), kcat (roped), v; head-major ----------------
__global__ __launch_bounds__(256)
void pack_kernel()
{
    const int t = blockIdx.x;
    const float pos = (float)t;     // positions == arange(T) by construction

    __shared__ float cs[DR / 2], sn[DR / 2];
    if (threadIdx.x < DR / 2) {
        const float inv = powf(THETA, -(float)(2 * threadIdx.x) / (float)DR);
        const float f = pos * inv;
        cs[threadIdx.x] = cosf(f);
        sn[threadIdx.x] = sinf(f);
    }
    __syncthreads();

    const float scale = rsqrtf((float)DQK);

    for (int idx = threadIdx.x; idx < H * DQK; idx += blockDim.x) {
        const int h = idx / DQK, d = idx % DQK;
        float qv;
        const size_t qbase = (size_t)t * (H * DQK) + (size_t)h * DQK;
        if (d < DN) {
            qv = g_q[qbase + d];
        } else {
            const int j = d - DN, i = j >> 1;
            const float x1 = g_q[qbase + DN + 2 * i];
            const float x2 = g_q[qbase + DN + 2 * i + 1];
            qv = (j & 1) ? (x2 * cs[i] + x1 * sn[i]) : (x1 * cs[i] - x2 * sn[i]);
        }
        g_qcat[((size_t)h * T + t) * DQK + d] = qv * scale;

        float kvv;
        if (d < DN) {
            kvv = g_kvb[(size_t)t * (H * DKV) + (size_t)h * DKV + d];
        } else {
            const int j = d - DN, i = j >> 1;
            const float x1 = g_kv[(size_t)t * (KVL + DR) + KVL + 2 * i];
            const float x2 = g_kv[(size_t)t * (KVL + DR) + KVL + 2 * i + 1];
            kvv = (j & 1) ? (x2 * cs[i] + x1 * sn[i]) : (x1 * cs[i] - x2 * sn[i]);
        }
        g_kcat[((size_t)h * T + t) * DQK + d] = kvv;
    }
    for (int idx = threadIdx.x; idx < H * DV; idx += blockDim.x) {
        const int h = idx / DV, d = idx % DV;
        g_v[((size_t)h * T + t) * DV + d] =
            g_kvb[(size_t)t * (H * DKV) + (size_t)h * DKV + DN + d];
    }
}

// ---------------- causal softmax over row t (valid length t+1), zero-fill the tail ----------------
__global__ __launch_bounds__(256)
void softmax_kernel()
{
    const int t = blockIdx.x;
    const int h = blockIdx.y;
    float* row = g_scores + ((size_t)h * T + t) * T;
    const int n = t + 1;

    __shared__ float red[32];

    float m = -INFINITY;
    for (int i = threadIdx.x; i < n; i += blockDim.x) m = fmaxf(m, row[i]);
    #pragma unroll
    for (int o = 16; o; o >>= 1) m = fmaxf(m, __shfl_xor_sync(~0u, m, o));
    if ((threadIdx.x & 31) == 0) red[threadIdx.x >> 5] = m;
    __syncthreads();
    if (threadIdx.x < 32) {
        m = (threadIdx.x < (blockDim.x >> 5)) ? red[threadIdx.x] : -INFINITY;
        #pragma unroll
        for (int o = 16; o; o >>= 1) m = fmaxf(m, __shfl_xor_sync(~0u, m, o));
        if (threadIdx.x == 0) red[0] = m;
    }
    __syncthreads();
    m = red[0];
    __syncthreads();

    float s = 0.f;
    for (int i = threadIdx.x; i < n; i += blockDim.x) {
        const float e = expf(row[i] - m);
        row[i] = e;
        s += e;
    }
    #pragma unroll
    for (int o = 16; o; o >>= 1) s += __shfl_xor_sync(~0u, s, o);
    if ((threadIdx.x & 31) == 0) red[threadIdx.x >> 5] = s;
    __syncthreads();
    if (threadIdx.x < 32) {
        s = (threadIdx.x < (blockDim.x >> 5)) ? red[threadIdx.x] : 0.f;
        #pragma unroll
        for (int o = 16; o; o >>= 1) s += __shfl_xor_sync(~0u, s, o);
        if (threadIdx.x == 0) red[0] = s;
    }
    __syncthreads();
    const float inv = 1.f / red[0];

    for (int i = threadIdx.x; i < n; i += blockDim.x) row[i] *= inv;
    for (int i = n + threadIdx.x; i < T; i += blockDim.x) row[i] = 0.f;
}

// ---------------- launch ----------------
static inline dim3 gemm_grid(int M, int N, int Z) {
    return dim3((N + 127) / 128, (M + 127) / 128, Z);
}

extern "C" void kernel_launch(void* const* d_in, const int* in_sizes, int n_in,
                              void* d_out, int out_size)
{
    (void)in_sizes; (void)n_in; (void)out_size;
    const float* hidden  = (const float*)d_in[1];
    const float* wq_a    = (const float*)d_in[2];
    const float* q_a_ln  = (const float*)d_in[3];
    const float* wq_b    = (const float*)d_in[4];
    const float* wkv_a   = (const float*)d_in[5];
    const float* kv_a_ln = (const float*)d_in[6];
    const float* wkv_b   = (const float*)d_in[7];
    const float* wo      = (const float*)d_in[8];
    float* out = (float*)d_out;

    float *qa, *qan, *q, *kv, *ckv, *kvb, *qcat, *kcat, *v, *scores, *attnout;
    cudaGetSymbolAddress((void**)&qa, g_qa);
    cudaGetSymbolAddress((void**)&qan, g_qan);
    cudaGetSymbolAddress((void**)&q, g_q);
    cudaGetSymbolAddress((void**)&kv, g_kv);
    cudaGetSymbolAddress((void**)&ckv, g_ckv);
    cudaGetSymbolAddress((void**)&kvb, g_kvb);
    cudaGetSymbolAddress((void**)&qcat, g_qcat);
    cudaGetSymbolAddress((void**)&kcat, g_kcat);
    cudaGetSymbolAddress((void**)&v, g_v);
    cudaGetSymbolAddress((void**)&scores, g_scores);
    cudaGetSymbolAddress((void**)&attnout, g_attnout);

    // 1) q_a = hidden @ wq_a
    mma_gemm<0,0,0><<<gemm_grid(T, QL, 1), 256>>>(T, QL, HID, hidden, HID, 0, wq_a, QL, 0, qa, QL, 0);
    // 2) rmsnorm(q_a)
    rmsnorm_kernel<<<T, 256>>>(qa, q_a_ln, qan, QL, QL, QL);
    // 3) q = qan @ wq_b
    mma_gemm<0,0,0><<<gemm_grid(T, H * DQK, 1), 256>>>(T, H * DQK, QL, qan, QL, 0, wq_b, H * DQK, 0, q, H * DQK, 0);
    // 4) kv = hidden @ wkv_a
    mma_gemm<0,0,0><<<gemm_grid(T, KVL + DR, 1), 256>>>(T, KVL + DR, HID, hidden, HID, 0, wkv_a, KVL + DR, 0, kv, KVL + DR, 0);
    // 5) c_kv = rmsnorm(kv[:, :KVL])
    rmsnorm_kernel<<<T, 256>>>(kv, kv_a_ln, ckv, KVL, KVL + DR, KVL);
    // 6) kvb = c_kv @ wkv_b
    mma_gemm<0,0,0><<<gemm_grid(T, H * DKV, 1), 256>>>(T, H * DKV, KVL, ckv, KVL, 0, wkv_b, H * DKV, 0, kvb, H * DKV, 0);
    // 7) pack qcat/kcat/v with fused RoPE + scale
    pack_kernel<<<T, 256>>>();
    // 8) scores[h] = qcat[h] @ kcat[h]^T   (batched NT, causal block skip)
    mma_gemm<1,1,0><<<gemm_grid(T, T, H), 256>>>(T, T, DQK,
        qcat, DQK, (size_t)T * DQK, kcat, DQK, (size_t)T * DQK, scores, T, (size_t)T * T);
    // 9) causal softmax (+ zero tail)
    softmax_kernel<<<dim3(T, H), 256>>>();
    // 10) attnout[:, h*DV:(h+1)*DV] = attn[h] @ v[h]   (batched NN, K truncated)
    mma_gemm<0,0,1><<<gemm_grid(T, DV, H), 256>>>(T, DV, T,
        scores, T, (size_t)T * T, v, DV, (size_t)T * DV, attnout, H * DV, (size_t)DV);
    // 11) out = attnout @ wo
    mma_gemm<0,0,0><<<gemm_grid(T, HID, 1), 256>>>(T, HID, H * DV, attnout, H * DV, 0, wo, HID, 0, out, HID, 0);
}

// round 4
// speedup vs baseline: 4.4828x; 1.1865x over previous
#include <cuda_runtime.h>
#include <math.h>
#include <stdint.h>

#define T   2048
#define H   16
#define DN  128
#define DR  64
#define DV  128
#define QL  1536
#define KVL 512
#define HID 5120
#define DQK 192            // DN + DR
#define DKV 256            // DN + DV
#define EPS 1e-6f
#define THETA 10000.0f

// ---------------- scratch (static __device__ — no runtime allocation) ----------------
__device__ float g_qa   [(size_t)T * QL];
__device__ float g_qan  [(size_t)T * QL];
__device__ float g_q    [(size_t)T * H * DQK];
__device__ float g_kv   [(size_t)T * (KVL + DR)];
__device__ float g_kvpart[(size_t)4 * T * (KVL + DR)];
__device__ float g_ckv  [(size_t)T * KVL];
__device__ float g_kvb  [(size_t)T * H * DKV];
__device__ float g_qcat [(size_t)H * T * DQK];
__device__ float g_kcat [(size_t)H * T * DQK];
__device__ float g_v    [(size_t)H * T * DV];
__device__ float g_scores[(size_t)H * T * T];     // 268 MB
__device__ float g_attnout[(size_t)T * H * DV];

// ---------------- helpers ----------------
__device__ __forceinline__ float to_tf32(float x) {
    float r;
    asm("cvt.rna.tf32.f32 %0, %1;" : "=f"(r) : "f"(x));
    return r;
}

__device__ __forceinline__ void mma_tf32(float* d, const float* a, const float* b) {
    asm volatile(
        "mma.sync.aligned.m16n8k8.row.col.f32.tf32.tf32.f32 "
        "{%0,%1,%2,%3},{%4,%5,%6,%7},{%8,%9},{%0,%1,%2,%3};"
        : "+f"(d[0]), "+f"(d[1]), "+f"(d[2]), "+f"(d[3])
        : "r"(__float_as_uint(a[0])), "r"(__float_as_uint(a[1])),
          "r"(__float_as_uint(a[2])), "r"(__float_as_uint(a[3])),
          "r"(__float_as_uint(b[0])), "r"(__float_as_uint(b[1])));
}

// ---------------- tf32 tensor-core GEMM: C = A * B (or A * B^T), batched over z ----
// BM=BN=128, BK=16, 128 threads (4 warps, 2x2), warp tile 64x64.
// Double-buffered SMEM, register-staged global prefetch, 1 syncthreads per tile.
// CAUSAL: skip output blocks strictly above the diagonal.
// KLIM:   truncate K at (blockIdx.y+1)*128 (attn rows are zero past the diagonal).
// z-batching doubles as split-K (strideA/B/C define the per-z offsets).
#define AS_STR 20   // As[m][k] (k padded 16->20): bank = (4m+k)%32 -> conflict-free
#define BS_NT  20   // Bs[n][k]: same
#define BS_NN  136  // Bs[k][n]: bank = (8k+n)%32 -> conflict-free

template<int TRANSB, int CAUSAL, int KLIM>
__global__ __launch_bounds__(128, 2)
void mma_gemm(int M, int N, int K,
              const float* __restrict__ A, int lda, size_t strideA,
              const float* __restrict__ B, int ldb, size_t strideB,
              float* __restrict__ C, int ldc, size_t strideC)
{
    if (CAUSAL) {
        if ((int)blockIdx.x * 128 > (int)blockIdx.y * 128 + 127) return;
    }
    int Keff = K;
    if (KLIM) {
        int lim = ((int)blockIdx.y + 1) * 128;
        if (lim < Keff) Keff = lim;
    }

    A += (size_t)blockIdx.z * strideA;
    B += (size_t)blockIdx.z * strideB;
    C += (size_t)blockIdx.z * strideC;

    __shared__ float As[2][128 * AS_STR];
    __shared__ float Bs[2][TRANSB ? 128 * BS_NT : 16 * BS_NN];

    const int tid  = threadIdx.x;
    const int lane = tid & 31;
    const int warp = tid >> 5;
    const int wm   = warp >> 1;         // 0..1
    const int wn   = warp & 1;          // 0..1
    const int row0 = blockIdx.y * 128;
    const int col0 = blockIdx.x * 128;
    const bool fullN = (col0 + 128) <= N;

    float acc[4][8][4];
    #pragma unroll
    for (int mi = 0; mi < 4; mi++)
        #pragma unroll
        for (int ni = 0; ni < 8; ni++)
            #pragma unroll
            for (int f = 0; f < 4; f++) acc[mi][ni][f] = 0.f;

    float4 stA[4], stB[4];

    // ---- global loads into staging regs (tile k0) ----
    auto ldgA = [&](int k0) {
        #pragma unroll
        for (int i = 0; i < 4; i++) {
            int idx = tid + 128 * i, r = idx >> 2, j = idx & 3;
            stA[i] = *reinterpret_cast<const float4*>(
                &A[(size_t)(row0 + r) * lda + k0 + 4 * j]);
        }
    };
    auto ldgB = [&](int k0) {
        if (TRANSB) {
            #pragma unroll
            for (int i = 0; i < 4; i++) {
                int idx = tid + 128 * i, n = idx >> 2, j = idx & 3;
                if (fullN || (col0 + n) < N)
                    stB[i] = *reinterpret_cast<const float4*>(
                        &B[(size_t)(col0 + n) * ldb + k0 + 4 * j]);
                else
                    stB[i] = make_float4(0.f, 0.f, 0.f, 0.f);
            }
        } else {
            #pragma unroll
            for (int i = 0; i < 4; i++) {
                int idx = tid + 128 * i, k = idx >> 5, j = idx & 31;
                int gc = col0 + 4 * j;
                if (fullN) {
                    stB[i] = *reinterpret_cast<const float4*>(
                        &B[(size_t)(k0 + k) * ldb + gc]);
                } else {
                    float4 v = make_float4(0.f, 0.f, 0.f, 0.f);
                    const float* bp = &B[(size_t)(k0 + k) * ldb];
                    if (gc + 0 < N) v.x = bp[gc + 0];
                    if (gc + 1 < N) v.y = bp[gc + 1];
                    if (gc + 2 < N) v.z = bp[gc + 2];
                    if (gc + 3 < N) v.w = bp[gc + 3];
                    stB[i] = v;
                }
            }
        }
    };

    // ---- staging regs -> SMEM buffer (with tf32 rounding) ----
    auto stsA = [&](int buf) {
        #pragma unroll
        for (int i = 0; i < 4; i++) {
            int idx = tid + 128 * i, r = idx >> 2, j = idx & 3;
            *reinterpret_cast<float4*>(&As[buf][r * AS_STR + 4 * j]) =
                make_float4(to_tf32(stA[i].x), to_tf32(stA[i].y),
                            to_tf32(stA[i].z), to_tf32(stA[i].w));
        }
    };
    auto stsB = [&](int buf) {
        if (TRANSB) {
            #pragma unroll
            for (int i = 0; i < 4; i++) {
                int idx = tid + 128 * i, n = idx >> 2, j = idx & 3;
                *reinterpret_cast<float4*>(&Bs[buf][n * BS_NT + 4 * j]) =
                    make_float4(to_tf32(stB[i].x), to_tf32(stB[i].y),
                                to_tf32(stB[i].z), to_tf32(stB[i].w));
            }
        } else {
            #pragma unroll
            for (int i = 0; i < 4; i++) {
                int idx = tid + 128 * i, k = idx >> 5, j = idx & 31;
                *reinterpret_cast<float4*>(&Bs[buf][k * BS_NN + 4 * j]) =
                    make_float4(to_tf32(stB[i].x), to_tf32(stB[i].y),
                                to_tf32(stB[i].z), to_tf32(stB[i].w));
            }
        }
    };

    auto compute = [&](int buf) {
        #pragma unroll
        for (int ks = 0; ks < 2; ks++) {
            const int kq = ks * 8 + (lane & 3);
            float a[4][4], b[8][2];
            #pragma unroll
            for (int mi = 0; mi < 4; mi++) {
                int r = wm * 64 + mi * 16 + (lane >> 2);
                a[mi][0] = As[buf][r * AS_STR + kq];
                a[mi][1] = As[buf][(r + 8) * AS_STR + kq];
                a[mi][2] = As[buf][r * AS_STR + kq + 4];
                a[mi][3] = As[buf][(r + 8) * AS_STR + kq + 4];
            }
            #pragma unroll
            for (int ni = 0; ni < 8; ni++) {
                int n = wn * 64 + ni * 8 + (lane >> 2);
                if (TRANSB) {
                    b[ni][0] = Bs[buf][n * BS_NT + kq];
                    b[ni][1] = Bs[buf][n * BS_NT + kq + 4];
                } else {
                    b[ni][0] = Bs[buf][kq * BS_NN + n];
                    b[ni][1] = Bs[buf][(kq + 4) * BS_NN + n];
                }
            }
            #pragma unroll
            for (int mi = 0; mi < 4; mi++)
                #pragma unroll
                for (int ni = 0; ni < 8; ni++)
                    mma_tf32(acc[mi][ni], a[mi], b[ni]);
        }
    };

    // ---- main loop: 2-stage pipeline, 1 sync per tile ----
    const int nt = Keff / 16;
    ldgA(0); ldgB(0);
    stsA(0); stsB(0);
    __syncthreads();
    for (int t = 0; t < nt; t++) {
        const int buf = t & 1;
        if (t + 1 < nt) { ldgA((t + 1) * 16); ldgB((t + 1) * 16); }
        compute(buf);
        if (t + 1 < nt) {
            stsA(buf ^ 1); stsB(buf ^ 1);
            __syncthreads();
        }
    }

    // ---- epilogue ----
    #pragma unroll
    for (int mi = 0; mi < 4; mi++) {
        #pragma unroll
        for (int ni = 0; ni < 8; ni++) {
            int r  = row0 + wm * 64 + mi * 16 + (lane >> 2);
            int cc = col0 + wn * 64 + ni * 8 + 2 * (lane & 3);
            if (cc < N) {
                *reinterpret_cast<float2*>(&C[(size_t)r * ldc + cc]) =
                    make_float2(acc[mi][ni][0], acc[mi][ni][1]);
                *reinterpret_cast<float2*>(&C[(size_t)(r + 8) * ldc + cc]) =
                    make_float2(acc[mi][ni][2], acc[mi][ni][3]);
            }
        }
    }
}

// ---------------- split-K reduction: out[i] = sum_{s<4} part[s*n + i] ----------------
__global__ __launch_bounds__(256)
void reduce4_kernel(const float* __restrict__ p, float* __restrict__ out, int n4)
{
    int i = blockIdx.x * blockDim.x + threadIdx.x;
    if (i < n4) {
        const float4* p4 = reinterpret_cast<const float4*>(p);
        float4 a = p4[i], b = p4[i + n4], c = p4[i + 2 * n4], d = p4[i + 3 * n4];
        float4 r = make_float4(a.x + b.x + c.x + d.x, a.y + b.y + c.y + d.y,
                               a.z + b.z + c.z + d.z, a.w + b.w + c.w + d.w);
        reinterpret_cast<float4*>(out)[i] = r;
    }
}

// ---------------- RMSNorm: one block per row ----------------
__global__ __launch_bounds__(256)
void rmsnorm_kernel(const float* __restrict__ x, const float* __restrict__ w,
                    float* __restrict__ y, int n, int ld_in, int ld_out)
{
    const int row = blockIdx.x;
    const float* xr = x + (size_t)row * ld_in;
    float* yr = y + (size_t)row * ld_out;

    float s = 0.f;
    for (int i = threadIdx.x; i < n; i += blockDim.x) { float v = xr[i]; s += v * v; }

    __shared__ float red[32];
    #pragma unroll
    for (int o = 16; o; o >>= 1) s += __shfl_xor_sync(~0u, s, o);
    if ((threadIdx.x & 31) == 0) red[threadIdx.x >> 5] = s;
    __syncthreads();
    if (threadIdx.x < 32) {
        s = (threadIdx.x < (blockDim.x >> 5)) ? red[threadIdx.x] : 0.f;
        #pragma unroll
        for (int o = 16; o; o >>= 1) s += __shfl_xor_sync(~0u, s, o);
        if (threadIdx.x == 0) red[0] = s;
    }
    __syncthreads();
    const float r = rsqrtf(red[0] / (float)n + EPS);
    for (int i = threadIdx.x; i < n; i += blockDim.x) yr[i] = xr[i] * r * w[i];
}

// ---------------- pack: build qcat (roped+scaled), kcat (roped), v; head-major ----------------
__global__ __launch_bounds__(256)
void pack_kernel()
{
    const int t = blockIdx.x;
    const float pos = (float)t;     // positions == arange(T) by construction

    __shared__ float cs[DR / 2], sn[DR / 2];
    if (threadIdx.x < DR / 2) {
        const float inv = powf(THETA, -(float)(2 * threadIdx.x) / (float)DR);
        const float f = pos * inv;
        cs[threadIdx.x] = cosf(f);
        sn[threadIdx.x] = sinf(f);
    }
    __syncthreads();

    const float scale = rsqrtf((float)DQK);

    for (int idx = threadIdx.x; idx < H * DQK; idx += blockDim.x) {
        const int h = idx / DQK, d = idx % DQK;
        float qv;
        const size_t qbase = (size_t)t * (H * DQK) + (size_t)h * DQK;
        if (d < DN) {
            qv = g_q[qbase + d];
        } else {
            const int j = d - DN, i = j >> 1;
            const float x1 = g_q[qbase + DN + 2 * i];
            const float x2 = g_q[qbase + DN + 2 * i + 1];
            qv = (j & 1) ? (x2 * cs[i] + x1 * sn[i]) : (x1 * cs[i] - x2 * sn[i]);
        }
        g_qcat[((size_t)h * T + t) * DQK + d] = qv * scale;

        float kvv;
        if (d < DN) {
            kvv = g_kvb[(size_t)t * (H * DKV) + (size_t)h * DKV + d];
        } else {
            const int j = d - DN, i = j >> 1;
            const float x1 = g_kv[(size_t)t * (KVL + DR) + KVL + 2 * i];
            const float x2 = g_kv[(size_t)t * (KVL + DR) + KVL + 2 * i + 1];
            kvv = (j & 1) ? (x2 * cs[i] + x1 * sn[i]) : (x1 * cs[i] - x2 * sn[i]);
        }
        g_kcat[((size_t)h * T + t) * DQK + d] = kvv;
    }
    for (int idx = threadIdx.x; idx < H * DV; idx += blockDim.x) {
        const int h = idx / DV, d = idx % DV;
        g_v[((size_t)h * T + t) * DV + d] =
            g_kvb[(size_t)t * (H * DKV) + (size_t)h * DKV + DN + d];
    }
}

// ---------------- causal softmax over row t (valid length t+1), zero-fill the tail ----------------
__global__ __launch_bounds__(256)
void softmax_kernel()
{
    const int t = blockIdx.x;
    const int h = blockIdx.y;
    float* row = g_scores + ((size_t)h * T + t) * T;
    const int n = t + 1;

    __shared__ float red[32];

    float m = -INFINITY;
    for (int i = threadIdx.x; i < n; i += blockDim.x) m = fmaxf(m, row[i]);
    #pragma unroll
    for (int o = 16; o; o >>= 1) m = fmaxf(m, __shfl_xor_sync(~0u, m, o));
    if ((threadIdx.x & 31) == 0) red[threadIdx.x >> 5] = m;
    __syncthreads();
    if (threadIdx.x < 32) {
        m = (threadIdx.x < (blockDim.x >> 5)) ? red[threadIdx.x] : -INFINITY;
        #pragma unroll
        for (int o = 16; o; o >>= 1) m = fmaxf(m, __shfl_xor_sync(~0u, m, o));
        if (threadIdx.x == 0) red[0] = m;
    }
    __syncthreads();
    m = red[0];
    __syncthreads();

    float s = 0.f;
    for (int i = threadIdx.x; i < n; i += blockDim.x) {
        const float e = expf(row[i] - m);
        row[i] = e;
        s += e;
    }
    #pragma unroll
    for (int o = 16; o; o >>= 1) s += __shfl_xor_sync(~0u, s, o);
    if ((threadIdx.x & 31) == 0) red[threadIdx.x >> 5] = s;
    __syncthreads();
    if (threadIdx.x < 32) {
        s = (threadIdx.x < (blockDim.x >> 5)) ? red[threadIdx.x] : 0.f;
        #pragma unroll
        for (int o = 16; o; o >>= 1) s += __shfl_xor_sync(~0u, s, o);
        if (threadIdx.x == 0) red[0] = s;
    }
    __syncthreads();
    const float inv = 1.f / red[0];

    for (int i = threadIdx.x; i < n; i += blockDim.x) row[i] *= inv;
    for (int i = n + threadIdx.x; i < T; i += blockDim.x) row[i] = 0.f;
}

// ---------------- launch ----------------
static inline dim3 gemm_grid(int M, int N, int Z) {
    return dim3((N + 127) / 128, (M + 127) / 128, Z);
}

extern "C" void kernel_launch(void* const* d_in, const int* in_sizes, int n_in,
                              void* d_out, int out_size)
{
    (void)in_sizes; (void)n_in; (void)out_size;
    const float* hidden  = (const float*)d_in[1];
    const float* wq_a    = (const float*)d_in[2];
    const float* q_a_ln  = (const float*)d_in[3];
    const float* wq_b    = (const float*)d_in[4];
    const float* wkv_a   = (const float*)d_in[5];
    const float* kv_a_ln = (const float*)d_in[6];
    const float* wkv_b   = (const float*)d_in[7];
    const float* wo      = (const float*)d_in[8];
    float* out = (float*)d_out;

    float *qa, *qan, *q, *kv, *kvpart, *ckv, *kvb, *qcat, *kcat, *v, *scores, *attnout;
    cudaGetSymbolAddress((void**)&qa, g_qa);
    cudaGetSymbolAddress((void**)&qan, g_qan);
    cudaGetSymbolAddress((void**)&q, g_q);
    cudaGetSymbolAddress((void**)&kv, g_kv);
    cudaGetSymbolAddress((void**)&kvpart, g_kvpart);
    cudaGetSymbolAddress((void**)&ckv, g_ckv);
    cudaGetSymbolAddress((void**)&kvb, g_kvb);
    cudaGetSymbolAddress((void**)&qcat, g_qcat);
    cudaGetSymbolAddress((void**)&kcat, g_kcat);
    cudaGetSymbolAddress((void**)&v, g_v);
    cudaGetSymbolAddress((void**)&scores, g_scores);
    cudaGetSymbolAddress((void**)&attnout, g_attnout);

    // 1) q_a = hidden @ wq_a          [T,HID]x[HID,QL]
    mma_gemm<0,0,0><<<gemm_grid(T, QL, 1), 128>>>(T, QL, HID, hidden, HID, 0, wq_a, QL, 0, qa, QL, 0);
    // 2) rmsnorm(q_a)
    rmsnorm_kernel<<<T, 256>>>(qa, q_a_ln, qan, QL, QL, QL);
    // 3) q = qan @ wq_b               [T,QL]x[QL,H*DQK]
    mma_gemm<0,0,0><<<gemm_grid(T, H * DQK, 1), 128>>>(T, H * DQK, QL, qan, QL, 0, wq_b, H * DQK, 0, q, H * DQK, 0);
    // 4) kv = hidden @ wkv_a  — split-K x4 (grid 80 -> 320 blocks) + reduce
    {
        const int KS = HID / 4;   // 1280
        mma_gemm<0,0,0><<<gemm_grid(T, KVL + DR, 4), 128>>>(T, KVL + DR, KS,
            hidden, HID, (size_t)KS,
            wkv_a, KVL + DR, (size_t)KS * (KVL + DR),
            kvpart, KVL + DR, (size_t)T * (KVL + DR));
        const int n4 = T * (KVL + DR) / 4;
        reduce4_kernel<<<(n4 + 255) / 256, 256>>>(kvpart, kv, n4);
    }
    // 5) c_kv = rmsnorm(kv[:, :KVL])
    rmsnorm_kernel<<<T, 256>>>(kv, kv_a_ln, ckv, KVL, KVL + DR, KVL);
    // 6) kvb = c_kv @ wkv_b           [T,KVL]x[KVL,H*DKV]
    mma_gemm<0,0,0><<<gemm_grid(T, H * DKV, 1), 128>>>(T, H * DKV, KVL, ckv, KVL, 0, wkv_b, H * DKV, 0, kvb, H * DKV, 0);
    // 7) pack qcat/kcat/v with fused RoPE + scale
    pack_kernel<<<T, 256>>>();
    // 8) scores[h] = qcat[h] @ kcat[h]^T   (batched NT, causal block skip)
    mma_gemm<1,1,0><<<gemm_grid(T, T, H), 128>>>(T, T, DQK,
        qcat, DQK, (size_t)T * DQK, kcat, DQK, (size_t)T * DQK, scores, T, (size_t)T * T);
    // 9) causal softmax (+ zero tail)
    softmax_kernel<<<dim3(T, H), 256>>>();
    // 10) attnout[:, h*DV:(h+1)*DV] = attn[h] @ v[h]   (batched NN, K truncated)
    mma_gemm<0,0,1><<<gemm_grid(T, DV, H), 128>>>(T, DV, T,
        scores, T, (size_t)T * T, v, DV, (size_t)T * DV, attnout, H * DV, (size_t)DV);
    // 11) out = attnout @ wo          [T,H*DV]x[H*DV,HID]
    mma_gemm<0,0,0><<<gemm_grid(T, HID, 1), 128>>>(T, HID, H * DV, attnout, H * DV, 0, wo, HID, 0, out, HID, 0);
}